// round 1
// baseline (speedup 1.0000x reference)
#include <cuda_runtime.h>
#include <math.h>

// Problem constants
#define BATCH   16
#define CC      16          // C
#define KK      8           // K
#define CK      128         // C*K
#define CIN     152         // C + C*K + K
#define HH      128
#define WW      128
#define HW      16384       // H*W
#define PTILE   128         // pixels per block
#define NTHREADS 512

// Output layout (concatenated flattened tuple): pi_new, mu_new, sigma_new, gamma
#define OUT_PI_OFF   0
#define OUT_MU_OFF   2097152            // 16*8*16384
#define OUT_SIG_OFF  35651584           // + 16*128*16384
#define OUT_G_OFF    37748736           // + 16*8*16384

// Shared memory layout (floats):
//   in_vec  [152][128]  : concat [x(16); mu(128); rho(8)] per pixel, pixel-contiguous rows
//   wt      [152][128]  : transposed Wmu (i-major, ch contiguous); reused as mu_s [128][129] after GEMM
//   scratchA[8][128]    : alpha -> later gamma contributions
//   pinew   [8][128]    : pi logits -> pi_new (softmaxed in place)
//   wsig_s  [8][152]
#define SM_INVEC   0
#define SM_WT      (CIN*PTILE)                  // 19456
#define SM_SCRA    (SM_WT + CIN*CK)             // 38912
#define SM_PINEW   (SM_SCRA + KK*PTILE)         // 39936
#define SM_WSIG    (SM_PINEW + KK*PTILE)        // 40960
#define SM_FLOATS  (SM_WSIG + KK*CIN)           // 42176
#define SM_BYTES   (SM_FLOATS*4)                // 168704

__device__ float g_Wt[CIN*CK];   // Wmu transposed to [i][o]

__global__ void transpose_wmu_kernel(const float* __restrict__ Wmu) {
    int idx = blockIdx.x * 256 + threadIdx.x;
    if (idx < CK*CIN) {
        int o = idx / CIN;
        int i = idx - o*CIN;
        g_Wt[i*CK + o] = Wmu[idx];
    }
}

__global__ __launch_bounds__(NTHREADS, 1)
void gmm_fused_kernel(const float* __restrict__ x,
                      const float* __restrict__ pi,
                      const float* __restrict__ mu,
                      const float* __restrict__ sigma,
                      const float* __restrict__ Wpi,
                      const float* __restrict__ bpi,
                      const float* __restrict__ bmu,
                      const float* __restrict__ Wsig,
                      const float* __restrict__ bsig,
                      const float* __restrict__ Wg,
                      const float* __restrict__ bg,
                      float* __restrict__ out)
{
    extern __shared__ float sm[];
    float* in_vec   = sm + SM_INVEC;
    float* wt       = sm + SM_WT;
    float* scratchA = sm + SM_SCRA;
    float* pinew    = sm + SM_PINEW;
    float* wsig_s   = sm + SM_WSIG;

    const int tid   = threadIdx.x;
    const int pix0  = blockIdx.x * PTILE;
    const int batch = pix0 >> 14;          // HW = 16384
    const int hw0   = pix0 & (HW - 1);

    const float* xb   = x     + batch*CC*HW + hw0;
    const float* pib  = pi    + batch*KK*HW + hw0;
    const float* mub  = mu    + batch*CK*HW + hw0;
    const float* sigb = sigma + batch*KK*HW + hw0;

    // ---------------- Phase A: fill shared memory ----------------
    for (int idx = tid; idx < (CC+CK)*PTILE; idx += NTHREADS) {
        int i = idx >> 7;            // row (channel of concat input)
        int p = idx & 127;
        float v = (i < CC) ? xb[i*HW + p] : mub[(i-CC)*HW + p];
        in_vec[idx] = v;
    }
    for (int idx = tid; idx < CIN*CK; idx += NTHREADS) wt[idx] = g_Wt[idx];
    for (int idx = tid; idx < KK*CIN; idx += NTHREADS) wsig_s[idx] = Wsig[idx];
    __syncthreads();

    const float INV2PI = 0.15915494309189535f;

    // ---------------- Phase 0: dens, alpha, rho ----------------
    for (int t = tid; t < KK*PTILE; t += NTHREADS) {
        int k = t >> 7;
        int p = t & 127;
        float s = sigb[k*HW + p];
        float invs2 = 1.0f / (s*s);
        float dist = 0.f;
        #pragma unroll
        for (int c = 0; c < CC; c++) {
            float d = in_vec[c*PTILE + p] - in_vec[(CC + k*CC + c)*PTILE + p];
            dist = fmaf(d, d, dist);
        }
        float r  = invs2 * INV2PI;
        float r2 = r*r;
        float r4 = r2*r2;
        float dens = (r4*r4) * expf(-0.5f * dist * invs2);   // (2*pi*s2)^-8 * exp(...)
        float piv  = pib[k*HW + p];
        float a    = piv * dens;
        scratchA[t] = a;                                     // alpha
        in_vec[(CC+CK+k)*PTILE + p] = a * dens;              // rho
    }
    __syncthreads();

    // ---------------- Phase 0b: pi logits ----------------
    for (int t = tid; t < KK*PTILE; t += NTHREADS) {
        int k = t >> 7;
        int p = t & 127;
        float acc = bpi[k];
        #pragma unroll
        for (int j = 0; j < KK; j++)
            acc = fmaf(Wpi[k*2*KK + j], pib[j*HW + p], acc);
        #pragma unroll
        for (int j = 0; j < KK; j++)
            acc = fmaf(Wpi[k*2*KK + KK + j], scratchA[j*PTILE + p], acc);
        pinew[t] = acc;
    }
    __syncthreads();

    // ---------------- Phase 0c: softmax + store pi_new ----------------
    if (tid < PTILE) {
        int p = tid;
        float l[KK];
        float m = -1e30f;
        #pragma unroll
        for (int k = 0; k < KK; k++) { l[k] = pinew[k*PTILE + p]; m = fmaxf(m, l[k]); }
        float s = 0.f;
        #pragma unroll
        for (int k = 0; k < KK; k++) { l[k] = expf(l[k] - m); s += l[k]; }
        float inv = 1.f / s;
        #pragma unroll
        for (int k = 0; k < KK; k++) {
            float v = l[k] * inv;
            pinew[k*PTILE + p] = v;
            out[OUT_PI_OFF + batch*KK*HW + k*HW + hw0 + p] = v;
        }
    }
    __syncthreads();

    // ---------------- Phase 1: Wmu GEMM (152 -> 128 per pixel) ----------------
    // Thread (tx,ty): tx in [0,32) -> 4 channels at tx*4 ; ty in [0,16) -> 8 pixels at ty*8
    const int tx = tid & 31;
    const int ty = tid >> 5;
    const float4* wt4 = (const float4*)wt;       // row i: 32 float4, thread reads #tx
    const float4* v4  = (const float4*)in_vec;   // row i: 32 float4, thread reads #(ty*2), #(ty*2+1)

    float acc[4][8];
    #pragma unroll
    for (int j = 0; j < 4; j++) {
        float b = bmu[tx*4 + j];
        #pragma unroll
        for (int q = 0; q < 8; q++) acc[j][q] = b;
    }

    #pragma unroll 4
    for (int i = 0; i < CIN; i++) {
        float4 w  = wt4[i*32 + tx];
        float4 va = v4[i*32 + ty*2];
        float4 vb = v4[i*32 + ty*2 + 1];
        float wv[4] = {w.x, w.y, w.z, w.w};
        float vv[8] = {va.x, va.y, va.z, va.w, vb.x, vb.y, vb.z, vb.w};
        #pragma unroll
        for (int j = 0; j < 4; j++)
            #pragma unroll
            for (int q = 0; q < 8; q++)
                acc[j][q] = fmaf(wv[j], vv[q], acc[j][q]);
    }

    __syncthreads();   // everyone done reading wt before we overwrite it

    // ReLU + store mu_new into smem (wt region reused): layout [p][129] (pad => conflict-free reads)
    float* mu_s = wt;
    #pragma unroll
    for (int q = 0; q < 8; q++) {
        int p = ty*8 + q;
        #pragma unroll
        for (int j = 0; j < 4; j++)
            mu_s[p*129 + tx*4 + j] = fmaxf(acc[j][q], 0.f);
    }
    __syncthreads();

    // Coalesced global store of mu_new
    for (int idx = tid; idx < CK*PTILE; idx += NTHREADS) {
        int ch = idx >> 7;
        int p  = idx & 127;
        out[OUT_MU_OFF + batch*CK*HW + ch*HW + hw0 + p] = mu_s[p*129 + ch];
    }

    // ---------------- Phase 2: sigma conv + exp, dens2, gamma contribs ----------------
    for (int t = tid; t < KK*PTILE; t += NTHREADS) {
        int k = t >> 7;
        int p = t & 127;
        const float* wk   = wsig_s + k*CIN;
        const float* mrow = mu_s + p*129;

        float a0 = bsig[k], a1 = 0.f, a2 = 0.f, a3 = 0.f;
        #pragma unroll
        for (int i = 0; i < CC; i += 4) {
            a0 = fmaf(wk[i],   in_vec[(i)*PTILE + p],   a0);
            a1 = fmaf(wk[i+1], in_vec[(i+1)*PTILE + p], a1);
            a2 = fmaf(wk[i+2], in_vec[(i+2)*PTILE + p], a2);
            a3 = fmaf(wk[i+3], in_vec[(i+3)*PTILE + p], a3);
        }
        #pragma unroll 8
        for (int i = 0; i < CK; i += 4) {
            a0 = fmaf(wk[CC+i],   mrow[i],   a0);
            a1 = fmaf(wk[CC+i+1], mrow[i+1], a1);
            a2 = fmaf(wk[CC+i+2], mrow[i+2], a2);
            a3 = fmaf(wk[CC+i+3], mrow[i+3], a3);
        }
        #pragma unroll
        for (int i = 0; i < KK; i += 4) {
            a0 = fmaf(wk[CC+CK+i],   in_vec[(CC+CK+i)*PTILE + p],   a0);
            a1 = fmaf(wk[CC+CK+i+1], in_vec[(CC+CK+i+1)*PTILE + p], a1);
            a2 = fmaf(wk[CC+CK+i+2], in_vec[(CC+CK+i+2)*PTILE + p], a2);
            a3 = fmaf(wk[CC+CK+i+3], in_vec[(CC+CK+i+3)*PTILE + p], a3);
        }
        float tval = fmaxf((a0 + a1) + (a2 + a3), 0.f);
        float snew = expf(tval);
        out[OUT_SIG_OFF + batch*KK*HW + k*HW + hw0 + p] = snew;

        float invs2 = 1.f / (snew*snew);
        float dist = 0.f;
        #pragma unroll
        for (int c = 0; c < CC; c++) {
            float d = in_vec[c*PTILE + p] - mrow[k*CC + c];
            dist = fmaf(d, d, dist);
        }
        float r  = invs2 * INV2PI;
        float r2 = r*r;
        float r4 = r2*r2;
        float dens2 = (r4*r4) * expf(-0.5f * dist * invs2);
        scratchA[t] = Wg[k] * pinew[k*PTILE + p] * dens2;   // gamma contribution
    }
    __syncthreads();

    // ---------------- Phase 3: gamma ----------------
    if (tid < PTILE) {
        float g = bg[0];
        #pragma unroll
        for (int k = 0; k < KK; k++) g += scratchA[k*PTILE + tid];
        out[OUT_G_OFF + batch*HW + hw0 + tid] = 1.f / (1.f + expf(-g));
    }
}

extern "C" void kernel_launch(void* const* d_in, const int* in_sizes, int n_in,
                              void* d_out, int out_size)
{
    const float* x     = (const float*)d_in[0];
    const float* pi    = (const float*)d_in[1];
    const float* mu    = (const float*)d_in[2];
    const float* sigma = (const float*)d_in[3];
    const float* Wpi   = (const float*)d_in[4];
    const float* bpi   = (const float*)d_in[5];
    const float* Wmu   = (const float*)d_in[6];
    const float* bmu   = (const float*)d_in[7];
    const float* Wsig  = (const float*)d_in[8];
    const float* bsig  = (const float*)d_in[9];
    const float* Wg    = (const float*)d_in[10];
    const float* bg    = (const float*)d_in[11];
    float* out = (float*)d_out;

    // One-time-per-launch transpose of Wmu into __device__ buffer (graph-capturable)
    transpose_wmu_kernel<<<(CK*CIN + 255)/256, 256>>>(Wmu);

    cudaFuncSetAttribute(gmm_fused_kernel,
                         cudaFuncAttributeMaxDynamicSharedMemorySize, SM_BYTES);

    const int nblocks = (BATCH * HW) / PTILE;   // 2048
    gmm_fused_kernel<<<nblocks, NTHREADS, SM_BYTES>>>(
        x, pi, mu, sigma, Wpi, bpi, bmu, Wsig, bsig, Wg, bg, out);
}

// round 8
// speedup vs baseline: 1.1819x; 1.1819x over previous
#include <cuda_runtime.h>
#include <cstdint>
#include <math.h>

// Problem constants
#define BATCH   16
#define CC      16          // C
#define KK      8           // K
#define CK      128         // C*K
#define CIN     152         // C + C*K + K  (= 19 * 8, exact for k8 MMA steps)
#define HW      16384
#define PTILE   128
#define NTHREADS 1024
#define ASTRIDE 165         // row stride (floats); 165 mod 32 = 5 (coprime) -> near-conflict-free

#define OUT_PI_OFF   0
#define OUT_MU_OFF   2097152
#define OUT_SIG_OFF  35651584
#define OUT_G_OFF    37748736

// Shared memory layout (float indices)
#define SM_A      0                          // A_s [128 px][165] tf32, 21120 f
#define SM_W      21120                      // W_s [128 ch][165] tf32, 21120 f (mu_s [128][129] overlay after GEMM)
#define SM_XP     42240                      // x plain [16][128]
#define SM_RHO    44288                      // rho plain [8][128]
#define SM_SCRA   45312                      // [8][128] alpha -> gamma contribs
#define SM_PINEW  46336                      // [8][128]
#define SM_WSIG   47360                      // [8][152]
#define SM_FLOATS 48576
#define SM_BYTES  (SM_FLOATS*4)              // 194304 B

__device__ float4 g_Wt4[(CK*ASTRIDE)/4];     // Wmu as tf32, [ch][165] layout (21120 floats)

__device__ __forceinline__ float to_tf32(float x) {
    uint32_t u;
    asm("cvt.rna.tf32.f32 %0, %1;" : "=r"(u) : "f"(x));
    return __uint_as_float(u);
}

// mma.sync m16n8k8 tf32 (base ISA, sm_80+): D = A(16x8,row) * B(8x8,col) + D
__device__ __forceinline__ void mma_tf32(float* c, uint32_t a0, uint32_t a1, uint32_t a2, uint32_t a3,
                                         uint32_t b0, uint32_t b1) {
    asm volatile("mma.sync.aligned.m16n8k8.row.col.f32.tf32.tf32.f32 "
                 "{%0,%1,%2,%3}, {%4,%5,%6,%7}, {%8,%9}, {%0,%1,%2,%3};"
                 : "+f"(c[0]), "+f"(c[1]), "+f"(c[2]), "+f"(c[3])
                 : "r"(a0), "r"(a1), "r"(a2), "r"(a3), "r"(b0), "r"(b1));
}

__global__ void prep_weights_kernel(const float* __restrict__ Wmu) {
    int idx = blockIdx.x * 256 + threadIdx.x;
    if (idx < CK * ASTRIDE) {
        int o = idx / ASTRIDE;
        int k = idx - o * ASTRIDE;
        float v = (k < CIN) ? to_tf32(Wmu[o * CIN + k]) : 0.f;
        ((float*)g_Wt4)[o * ASTRIDE + k] = v;
    }
}

__global__ __launch_bounds__(NTHREADS, 1)
void gmm_fused_kernel(const float* __restrict__ x,
                      const float* __restrict__ pi,
                      const float* __restrict__ mu,
                      const float* __restrict__ sigma,
                      const float* __restrict__ Wpi,
                      const float* __restrict__ bpi,
                      const float* __restrict__ bmu,
                      const float* __restrict__ Wsig,
                      const float* __restrict__ bsig,
                      const float* __restrict__ Wg,
                      const float* __restrict__ bg,
                      float* __restrict__ out)
{
    extern __shared__ float sm[];
    float* A_s      = sm + SM_A;
    float* W_s      = sm + SM_W;
    float* xplain   = sm + SM_XP;
    float* rhopl    = sm + SM_RHO;
    float* scratchA = sm + SM_SCRA;
    float* pinew    = sm + SM_PINEW;
    float* wsig_s   = sm + SM_WSIG;

    const int tid   = threadIdx.x;
    const int wid   = tid >> 5;
    const int lane  = tid & 31;
    const int pix0  = blockIdx.x * PTILE;
    const int batch = pix0 >> 14;
    const int hw0   = pix0 & (HW - 1);

    const float* xb   = x     + batch*CC*HW + hw0;
    const float* pib  = pi    + batch*KK*HW + hw0;
    const float* mub  = mu    + batch*CK*HW + hw0;
    const float* sigb = sigma + batch*KK*HW + hw0;

    // ---------------- Staging ----------------
    // A_s cols 0..143 : tf32 of [x(16); mu(128)]; rows = pixels, stride 165
    for (int idx = tid; idx < (CC+CK)*PTILE; idx += NTHREADS) {
        int c = idx >> 7;
        int p = idx & 127;
        float v = (c < CC) ? xb[c*HW + p] : mub[(c-CC)*HW + p];
        A_s[p*ASTRIDE + c] = to_tf32(v);
        if (c < CC) xplain[c*PTILE + p] = v;
    }
    // W_s: pre-converted tf32 weights, linear float4 copy
    {
        float4* dst = (float4*)W_s;
        for (int i = tid; i < (CK*ASTRIDE)/4; i += NTHREADS)
            dst[i] = g_Wt4[i];
    }
    for (int idx = tid; idx < KK*CIN; idx += NTHREADS) wsig_s[idx] = Wsig[idx];
    __syncthreads();

    const float INV2PI = 0.15915494309189535f;

    // ---------------- Phase 0: dens, alpha, rho (one item per thread) ----------------
    {
        int t = tid;                 // KK*PTILE == 1024 == NTHREADS
        int k = t >> 7;
        int p = t & 127;
        float s = sigb[k*HW + p];
        float invs2 = 1.0f / (s*s);
        float dist = 0.f;
        #pragma unroll
        for (int c = 0; c < CC; c++) {
            float d = xplain[c*PTILE + p] - mub[(k*CC + c)*HW + p];
            dist = fmaf(d, d, dist);
        }
        float r  = invs2 * INV2PI;
        float r2 = r*r;
        float r4 = r2*r2;
        float dens = (r4*r4) * expf(-0.5f * dist * invs2);
        float piv  = pib[k*HW + p];
        float a    = piv * dens;
        float rho  = a * dens;
        scratchA[t] = a;
        rhopl[t]    = rho;
        A_s[p*ASTRIDE + CC + CK + k] = to_tf32(rho);
    }
    __syncthreads();

    // ---------------- Phase 0b: pi logits (one item per thread) ----------------
    {
        int t = tid;
        int k = t >> 7;
        int p = t & 127;
        float acc = bpi[k];
        #pragma unroll
        for (int j = 0; j < KK; j++)
            acc = fmaf(Wpi[k*2*KK + j], pib[j*HW + p], acc);
        #pragma unroll
        for (int j = 0; j < KK; j++)
            acc = fmaf(Wpi[k*2*KK + KK + j], scratchA[j*PTILE + p], acc);
        pinew[t] = acc;
    }

    // ---------------- GEMM: mu logits via tf32 mma.sync ----------------
    // Warp wid: pixel tile pxt = wid>>2 (16 px), channel block chb = (wid&3)*32 (4 n8 tiles)
    const int g   = lane >> 2;       // 0..7
    const int tg  = lane & 3;        // 0..3
    const int pxt = wid >> 2;        // 0..7
    const int chb = (wid & 3) * 32;  // 0,32,64,96

    float acc[4][4];
    #pragma unroll
    for (int t = 0; t < 4; t++) {
        float b0v = bmu[chb + t*8 + 2*tg];
        float b1v = bmu[chb + t*8 + 2*tg + 1];
        acc[t][0] = b0v; acc[t][1] = b1v;
        acc[t][2] = b0v; acc[t][3] = b1v;
    }

    const float* Abase = A_s + (pxt*16 + g)*ASTRIDE + tg;
    #pragma unroll
    for (int kb = 0; kb < CIN/8; kb++) {
        const int ko = kb * 8;
        uint32_t a0 = __float_as_uint(Abase[ko]);
        uint32_t a1 = __float_as_uint(Abase[8*ASTRIDE + ko]);
        uint32_t a2 = __float_as_uint(Abase[ko + 4]);
        uint32_t a3 = __float_as_uint(Abase[8*ASTRIDE + ko + 4]);
        #pragma unroll
        for (int t = 0; t < 4; t++) {
            const float* Bp = W_s + (chb + t*8 + g)*ASTRIDE + ko + tg;
            uint32_t b0 = __float_as_uint(Bp[0]);
            uint32_t b1 = __float_as_uint(Bp[4]);
            mma_tf32(acc[t], a0, a1, a2, a3, b0, b1);
        }
    }
    __syncthreads();   // all warps done reading W_s / A_s; pinew written

    // ---------------- Epilogue: ReLU -> mu_s (overlay W_s, stride 129) + softmax ----------------
    float* mu_s = W_s;
    {
        int px = pxt*16 + g;
        #pragma unroll
        for (int t = 0; t < 4; t++) {
            int ch = chb + t*8 + 2*tg;
            mu_s[px*129 + ch]       = fmaxf(acc[t][0], 0.f);
            mu_s[px*129 + ch + 1]   = fmaxf(acc[t][1], 0.f);
            mu_s[(px+8)*129 + ch]   = fmaxf(acc[t][2], 0.f);
            mu_s[(px+8)*129 + ch+1] = fmaxf(acc[t][3], 0.f);
        }
    }
    if (tid < PTILE) {
        int p = tid;
        float l[KK];
        float m = -1e30f;
        #pragma unroll
        for (int k = 0; k < KK; k++) { l[k] = pinew[k*PTILE + p]; m = fmaxf(m, l[k]); }
        float ssum = 0.f;
        #pragma unroll
        for (int k = 0; k < KK; k++) { l[k] = expf(l[k] - m); ssum += l[k]; }
        float inv = 1.f / ssum;
        #pragma unroll
        for (int k = 0; k < KK; k++) {
            float v = l[k] * inv;
            pinew[k*PTILE + p] = v;
            out[OUT_PI_OFF + batch*KK*HW + k*HW + hw0 + p] = v;
        }
    }
    __syncthreads();

    // Coalesced global store of mu_new
    for (int idx = tid; idx < CK*PTILE; idx += NTHREADS) {
        int ch = idx >> 7;
        int p  = idx & 127;
        out[OUT_MU_OFF + batch*CK*HW + ch*HW + hw0 + p] = mu_s[p*129 + ch];
    }

    // ---------------- Phase 2: sigma conv + exp, dens2, gamma contribs ----------------
    {
        int t = tid;
        int k = t >> 7;
        int p = t & 127;
        const float* wk   = wsig_s + k*CIN;
        const float* mrow = mu_s + p*129;

        float a0 = bsig[k], a1 = 0.f, a2 = 0.f, a3 = 0.f;
        #pragma unroll
        for (int i = 0; i < CC; i += 4) {
            a0 = fmaf(wk[i],   xplain[(i)*PTILE + p],   a0);
            a1 = fmaf(wk[i+1], xplain[(i+1)*PTILE + p], a1);
            a2 = fmaf(wk[i+2], xplain[(i+2)*PTILE + p], a2);
            a3 = fmaf(wk[i+3], xplain[(i+3)*PTILE + p], a3);
        }
        #pragma unroll 8
        for (int i = 0; i < CK; i += 4) {
            a0 = fmaf(wk[CC+i],   mrow[i],   a0);
            a1 = fmaf(wk[CC+i+1], mrow[i+1], a1);
            a2 = fmaf(wk[CC+i+2], mrow[i+2], a2);
            a3 = fmaf(wk[CC+i+3], mrow[i+3], a3);
        }
        #pragma unroll
        for (int i = 0; i < KK; i += 4) {
            a0 = fmaf(wk[CC+CK+i],   rhopl[(i)*PTILE + p],   a0);
            a1 = fmaf(wk[CC+CK+i+1], rhopl[(i+1)*PTILE + p], a1);
            a2 = fmaf(wk[CC+CK+i+2], rhopl[(i+2)*PTILE + p], a2);
            a3 = fmaf(wk[CC+CK+i+3], rhopl[(i+3)*PTILE + p], a3);
        }
        float tval = fmaxf((a0 + a1) + (a2 + a3), 0.f);
        float snew = expf(tval);
        out[OUT_SIG_OFF + batch*KK*HW + k*HW + hw0 + p] = snew;

        float invs2 = 1.f / (snew*snew);
        float dist = 0.f;
        #pragma unroll
        for (int c = 0; c < CC; c++) {
            float d = xplain[c*PTILE + p] - mrow[k*CC + c];
            dist = fmaf(d, d, dist);
        }
        float r  = invs2 * INV2PI;
        float r2 = r*r;
        float r4 = r2*r2;
        float dens2 = (r4*r4) * expf(-0.5f * dist * invs2);
        scratchA[t] = Wg[k] * pinew[k*PTILE + p] * dens2;
    }
    __syncthreads();

    // ---------------- Phase 3: gamma ----------------
    if (tid < PTILE) {
        float gacc = bg[0];
        #pragma unroll
        for (int k = 0; k < KK; k++) gacc += scratchA[k*PTILE + tid];
        out[OUT_G_OFF + batch*HW + hw0 + tid] = 1.f / (1.f + expf(-gacc));
    }
}

extern "C" void kernel_launch(void* const* d_in, const int* in_sizes, int n_in,
                              void* d_out, int out_size)
{
    const float* x     = (const float*)d_in[0];
    const float* pi    = (const float*)d_in[1];
    const float* mu    = (const float*)d_in[2];
    const float* sigma = (const float*)d_in[3];
    const float* Wpi   = (const float*)d_in[4];
    const float* bpi   = (const float*)d_in[5];
    const float* Wmu   = (const float*)d_in[6];
    const float* bmu   = (const float*)d_in[7];
    const float* Wsig  = (const float*)d_in[8];
    const float* bsig  = (const float*)d_in[9];
    const float* Wg    = (const float*)d_in[10];
    const float* bg    = (const float*)d_in[11];
    float* out = (float*)d_out;

    prep_weights_kernel<<<(CK*ASTRIDE + 255)/256, 256>>>(Wmu);

    cudaFuncSetAttribute(gmm_fused_kernel,
                         cudaFuncAttributeMaxDynamicSharedMemorySize, SM_BYTES);

    const int nblocks = (BATCH * HW) / PTILE;   // 2048
    gmm_fused_kernel<<<nblocks, NTHREADS, SM_BYTES>>>(
        x, pi, mu, sigma, Wpi, bpi, bmu, Wsig, bsig, Wg, bg, out);
}

// round 9
// speedup vs baseline: 1.7076x; 1.4448x over previous
#include <cuda_runtime.h>
#include <cstdint>
#include <math.h>

// Problem constants
#define BATCH   16
#define CC      16          // C
#define KK      8           // K
#define CK      128         // C*K
#define CIN     152         // C + C*K + K  (= 19 * 8)
#define HW      16384
#define PTILE   128
#define NTHREADS 1024
#define ASTRIDE 165         // A row stride (floats); odd-ish -> conflict-free scalar
#define MUSTRIDE 132        // mu_s row stride: 16B aligned, (33p+i)%32 distinct per p

#define OUT_PI_OFF   0
#define OUT_MU_OFF   2097152
#define OUT_SIG_OFF  35651584
#define OUT_G_OFF    37748736

// Fragment-major weight layout: WF[chbIdx(4)][kb(19)][pair(2)][lane(32)][4]
#define WF_FLOATS (4*19*2*32*4)              // 19456

// Shared memory layout (float indices)
#define SM_A      0                          // A_s [128 px][165] tf32, 21120 f
#define SM_W      21120                      // WF_s 19456 f (mu_s [128][132]=16896 overlay after GEMM)
#define SM_XP     40576                      // x plain [16][128]
#define SM_RHO    42624                      // rho plain [8][128]
#define SM_SCRA   43648                      // [8][128] alpha -> gamma contribs
#define SM_PINEW  44672                      // [8][128]
#define SM_WSIG   45696                      // [8][152]
#define SM_FLOATS 46912
#define SM_BYTES  (SM_FLOATS*4)              // 187648 B

__device__ float4 g_WF[WF_FLOATS/4];         // Wmu tf32 in fragment-major layout

__device__ __forceinline__ float to_tf32(float x) {
    uint32_t u;
    asm("cvt.rna.tf32.f32 %0, %1;" : "=r"(u) : "f"(x));
    return __uint_as_float(u);
}

// mma.sync m16n8k8 tf32 (base ISA, sm_80+)
__device__ __forceinline__ void mma_tf32(float* c, uint32_t a0, uint32_t a1, uint32_t a2, uint32_t a3,
                                         uint32_t b0, uint32_t b1) {
    asm volatile("mma.sync.aligned.m16n8k8.row.col.f32.tf32.tf32.f32 "
                 "{%0,%1,%2,%3}, {%4,%5,%6,%7}, {%8,%9}, {%0,%1,%2,%3};"
                 : "+f"(c[0]), "+f"(c[1]), "+f"(c[2]), "+f"(c[3])
                 : "r"(a0), "r"(a1), "r"(a2), "r"(a3), "r"(b0), "r"(b1));
}

// Prep: Wmu[o][k] (o=out channel 0..127, k=0..151) -> fragment-major tf32.
// For warp block chbIdx=o>>5: cho=o&31, t=cho>>3 (n8 tile), g=cho&7; pair=t>>1, th=t&1.
// kb=k>>3, r=k&7, tg=r&3, bslot=r>>2 (b0/b1). slot = th*2 + bslot. lane = g*4+tg.
__global__ void prep_weights_kernel(const float* __restrict__ Wmu) {
    int idx = blockIdx.x * 256 + threadIdx.x;
    if (idx < CK * CIN) {
        int o = idx / CIN;
        int k = idx - o * CIN;
        int chbIdx = o >> 5, cho = o & 31, t = cho >> 3, g = cho & 7;
        int pair = t >> 1, th = t & 1;
        int kb = k >> 3, r = k & 7, tg = r & 3, bslot = r >> 2;
        int lane = g*4 + tg;
        int slot = th*2 + bslot;
        int fidx = ((((chbIdx*19 + kb)*2 + pair)*32 + lane)<<2) + slot;
        ((float*)g_WF)[fidx] = to_tf32(Wmu[idx]);
    }
}

__global__ __launch_bounds__(NTHREADS, 1)
void gmm_fused_kernel(const float* __restrict__ x,
                      const float* __restrict__ pi,
                      const float* __restrict__ mu,
                      const float* __restrict__ sigma,
                      const float* __restrict__ Wpi,
                      const float* __restrict__ bpi,
                      const float* __restrict__ bmu,
                      const float* __restrict__ Wsig,
                      const float* __restrict__ bsig,
                      const float* __restrict__ Wg,
                      const float* __restrict__ bg,
                      float* __restrict__ out)
{
    extern __shared__ float sm[];
    float* A_s      = sm + SM_A;
    float* WF_s     = sm + SM_W;
    float* xplain   = sm + SM_XP;
    float* rhopl    = sm + SM_RHO;
    float* scratchA = sm + SM_SCRA;
    float* pinew    = sm + SM_PINEW;
    float* wsig_s   = sm + SM_WSIG;

    const int tid   = threadIdx.x;
    const int wid   = tid >> 5;
    const int lane  = tid & 31;
    const int pix0  = blockIdx.x * PTILE;
    const int batch = pix0 >> 14;
    const int hw0   = pix0 & (HW - 1);

    const float* xb   = x     + batch*CC*HW + hw0;
    const float* pib  = pi    + batch*KK*HW + hw0;
    const float* mub  = mu    + batch*CK*HW + hw0;
    const float* sigb = sigma + batch*KK*HW + hw0;

    // ---------------- Staging (vectorized loads) ----------------
    // (CC+CK)=144 channels x 128 px, float4 along px: 4608 float4 items
    for (int idx = tid; idx < (CC+CK)*PTILE/4; idx += NTHREADS) {
        int c  = idx >> 5;
        int p4 = (idx & 31) << 2;
        float4 v = (c < CC) ? *(const float4*)(xb + c*HW + p4)
                            : *(const float4*)(mub + (c-CC)*HW + p4);
        A_s[(p4+0)*ASTRIDE + c] = to_tf32(v.x);
        A_s[(p4+1)*ASTRIDE + c] = to_tf32(v.y);
        A_s[(p4+2)*ASTRIDE + c] = to_tf32(v.z);
        A_s[(p4+3)*ASTRIDE + c] = to_tf32(v.w);
        if (c < CC) *(float4*)(xplain + c*PTILE + p4) = v;
    }
    // WF_s: fragment-major weights, linear float4 copy (4864 float4)
    {
        float4* dst = (float4*)WF_s;
        for (int i = tid; i < WF_FLOATS/4; i += NTHREADS)
            dst[i] = g_WF[i];
    }
    for (int idx = tid; idx < KK*CIN; idx += NTHREADS) wsig_s[idx] = Wsig[idx];
    __syncthreads();

    const float INV2PI = 0.15915494309189535f;

    // ---------------- Phase 0: dens, alpha, rho (one item per thread) ----------------
    {
        int t = tid;                 // KK*PTILE == 1024 == NTHREADS
        int k = t >> 7;
        int p = t & 127;
        float s = sigb[k*HW + p];
        float invs2 = 1.0f / (s*s);
        float dist = 0.f;
        #pragma unroll
        for (int c = 0; c < CC; c++) {
            float d = xplain[c*PTILE + p] - mub[(k*CC + c)*HW + p];
            dist = fmaf(d, d, dist);
        }
        float r  = invs2 * INV2PI;
        float r2 = r*r;
        float r4 = r2*r2;
        float dens = (r4*r4) * expf(-0.5f * dist * invs2);
        float piv  = pib[k*HW + p];
        float a    = piv * dens;
        float rho  = a * dens;
        scratchA[t] = a;
        rhopl[t]    = rho;
        A_s[p*ASTRIDE + CC + CK + k] = to_tf32(rho);
    }
    __syncthreads();

    // ---------------- Phase 0b: pi logits ----------------
    {
        int t = tid;
        int k = t >> 7;
        int p = t & 127;
        float acc = bpi[k];
        #pragma unroll
        for (int j = 0; j < KK; j++)
            acc = fmaf(Wpi[k*2*KK + j], pib[j*HW + p], acc);
        #pragma unroll
        for (int j = 0; j < KK; j++)
            acc = fmaf(Wpi[k*2*KK + KK + j], scratchA[j*PTILE + p], acc);
        pinew[t] = acc;
    }

    // ---------------- GEMM: tf32 mma.sync, fragment-major B ----------------
    const int g      = lane >> 2;       // 0..7
    const int tg     = lane & 3;        // 0..3
    const int pxt    = wid >> 2;        // 0..7   (16-pixel tile)
    const int chbIdx = wid & 3;         // 0..3   (32-channel block)
    const int chb    = chbIdx * 32;

    float acc[4][4];
    #pragma unroll
    for (int t = 0; t < 4; t++) {
        float b0v = bmu[chb + t*8 + 2*tg];
        float b1v = bmu[chb + t*8 + 2*tg + 1];
        acc[t][0] = b0v; acc[t][1] = b1v;
        acc[t][2] = b0v; acc[t][3] = b1v;
    }

    const float*  Abase = A_s + (pxt*16 + g)*ASTRIDE + tg;
    const float4* WFb   = (const float4*)WF_s + (chbIdx*19*2)*32 + lane;
    #pragma unroll
    for (int kb = 0; kb < CIN/8; kb++) {
        const int ko = kb * 8;
        uint32_t a0 = __float_as_uint(Abase[ko]);
        uint32_t a1 = __float_as_uint(Abase[8*ASTRIDE + ko]);
        uint32_t a2 = __float_as_uint(Abase[ko + 4]);
        uint32_t a3 = __float_as_uint(Abase[8*ASTRIDE + ko + 4]);
        float4 w0 = WFb[(kb*2 + 0)*32];
        float4 w1 = WFb[(kb*2 + 1)*32];
        mma_tf32(acc[0], a0, a1, a2, a3, __float_as_uint(w0.x), __float_as_uint(w0.y));
        mma_tf32(acc[1], a0, a1, a2, a3, __float_as_uint(w0.z), __float_as_uint(w0.w));
        mma_tf32(acc[2], a0, a1, a2, a3, __float_as_uint(w1.x), __float_as_uint(w1.y));
        mma_tf32(acc[3], a0, a1, a2, a3, __float_as_uint(w1.z), __float_as_uint(w1.w));
    }
    __syncthreads();   // all warps done reading WF_s / A_s; pinew written

    // ---------------- Epilogue: ReLU -> mu_s (overlay WF_s, stride 132) + softmax ----------------
    float* mu_s = WF_s;
    {
        int px = pxt*16 + g;
        #pragma unroll
        for (int t = 0; t < 4; t++) {
            int ch = chb + t*8 + 2*tg;
            mu_s[px*MUSTRIDE + ch]         = fmaxf(acc[t][0], 0.f);
            mu_s[px*MUSTRIDE + ch + 1]     = fmaxf(acc[t][1], 0.f);
            mu_s[(px+8)*MUSTRIDE + ch]     = fmaxf(acc[t][2], 0.f);
            mu_s[(px+8)*MUSTRIDE + ch + 1] = fmaxf(acc[t][3], 0.f);
        }
    }
    if (tid < PTILE) {
        int p = tid;
        float l[KK];
        float m = -1e30f;
        #pragma unroll
        for (int k = 0; k < KK; k++) { l[k] = pinew[k*PTILE + p]; m = fmaxf(m, l[k]); }
        float ssum = 0.f;
        #pragma unroll
        for (int k = 0; k < KK; k++) { l[k] = expf(l[k] - m); ssum += l[k]; }
        float inv = 1.f / ssum;
        #pragma unroll
        for (int k = 0; k < KK; k++) {
            float v = l[k] * inv;
            pinew[k*PTILE + p] = v;
            out[OUT_PI_OFF + batch*KK*HW + k*HW + hw0 + p] = v;
        }
    }
    __syncthreads();

    // Coalesced global store of mu_new
    for (int idx = tid; idx < CK*PTILE; idx += NTHREADS) {
        int ch = idx >> 7;
        int p  = idx & 127;
        out[OUT_MU_OFF + batch*CK*HW + ch*HW + hw0 + p] = mu_s[p*MUSTRIDE + ch];
    }

    // ---------------- Phase 2: sigma conv (float4) + exp, dens2, gamma contribs ----------------
    {
        int t = tid;
        int k = t >> 7;
        int p = t & 127;
        const float* wk   = wsig_s + k*CIN;
        const float* mrow = mu_s + p*MUSTRIDE;

        float a0 = bsig[k], a1 = 0.f, a2 = 0.f, a3 = 0.f;
        #pragma unroll
        for (int i = 0; i < CC; i += 4) {
            a0 = fmaf(wk[i],   xplain[(i)*PTILE + p],   a0);
            a1 = fmaf(wk[i+1], xplain[(i+1)*PTILE + p], a1);
            a2 = fmaf(wk[i+2], xplain[(i+2)*PTILE + p], a2);
            a3 = fmaf(wk[i+3], xplain[(i+3)*PTILE + p], a3);
        }
        #pragma unroll 8
        for (int i = 0; i < CK; i += 4) {
            float4 w4 = *(const float4*)(wk + CC + i);
            float4 m4 = *(const float4*)(mrow + i);
            a0 = fmaf(w4.x, m4.x, a0);
            a1 = fmaf(w4.y, m4.y, a1);
            a2 = fmaf(w4.z, m4.z, a2);
            a3 = fmaf(w4.w, m4.w, a3);
        }
        #pragma unroll
        for (int i = 0; i < KK; i += 4) {
            a0 = fmaf(wk[CC+CK+i],   rhopl[(i)*PTILE + p],   a0);
            a1 = fmaf(wk[CC+CK+i+1], rhopl[(i+1)*PTILE + p], a1);
            a2 = fmaf(wk[CC+CK+i+2], rhopl[(i+2)*PTILE + p], a2);
            a3 = fmaf(wk[CC+CK+i+3], rhopl[(i+3)*PTILE + p], a3);
        }
        float tval = fmaxf((a0 + a1) + (a2 + a3), 0.f);
        float snew = expf(tval);
        out[OUT_SIG_OFF + batch*KK*HW + k*HW + hw0 + p] = snew;

        float invs2 = 1.f / (snew*snew);
        float dist = 0.f;
        #pragma unroll
        for (int c = 0; c < CC; c++) {
            float d = xplain[c*PTILE + p] - mrow[k*CC + c];
            dist = fmaf(d, d, dist);
        }
        float r  = invs2 * INV2PI;
        float r2 = r*r;
        float r4 = r2*r2;
        float dens2 = (r4*r4) * expf(-0.5f * dist * invs2);
        scratchA[t] = Wg[k] * pinew[k*PTILE + p] * dens2;
    }
    __syncthreads();

    // ---------------- Phase 3: gamma ----------------
    if (tid < PTILE) {
        float gacc = bg[0];
        #pragma unroll
        for (int k = 0; k < KK; k++) gacc += scratchA[k*PTILE + tid];
        out[OUT_G_OFF + batch*HW + hw0 + tid] = 1.f / (1.f + expf(-gacc));
    }
}

extern "C" void kernel_launch(void* const* d_in, const int* in_sizes, int n_in,
                              void* d_out, int out_size)
{
    const float* x     = (const float*)d_in[0];
    const float* pi    = (const float*)d_in[1];
    const float* mu    = (const float*)d_in[2];
    const float* sigma = (const float*)d_in[3];
    const float* Wpi   = (const float*)d_in[4];
    const float* bpi   = (const float*)d_in[5];
    const float* Wmu   = (const float*)d_in[6];
    const float* bmu   = (const float*)d_in[7];
    const float* Wsig  = (const float*)d_in[8];
    const float* bsig  = (const float*)d_in[9];
    const float* Wg    = (const float*)d_in[10];
    const float* bg    = (const float*)d_in[11];
    float* out = (float*)d_out;

    prep_weights_kernel<<<(CK*CIN + 255)/256, 256>>>(Wmu);

    cudaFuncSetAttribute(gmm_fused_kernel,
                         cudaFuncAttributeMaxDynamicSharedMemorySize, SM_BYTES);

    const int nblocks = (BATCH * HW) / PTILE;   // 2048
    gmm_fused_kernel<<<nblocks, NTHREADS, SM_BYTES>>>(
        x, pi, mu, sigma, Wpi, bpi, bmu, Wsig, bsig, Wg, bg, out);
}